// round 2
// baseline (speedup 1.0000x reference)
#include <cuda_runtime.h>
#include <cuda_bf16.h>
#include <cstdint>
#include <cstddef>

// ---------------- problem constants ----------------
#define Cc   256
#define Hh   8
#define Dd   32
#define Kw   32
#define Ss   33          // S = G + K = 1 + 32
#define NWIN 8192
#define NTOK (NWIN*Kw)   // 262144
#define HIDN 1024
#define RROWS (NWIN*Ss)  // 270336  (divisible by 128)
#define SCALE_QK 0.17677669529663687f

// ---------------- device scratch (no cudaMalloc allowed) ----------------
__device__ float          g_X1 [(size_t)RROWS*Cc];        // x  (NW,S,C) fp32 block 0
__device__ float          g_X2 [(size_t)RROWS*Cc];        // x  fp32 block 1
__device__ __nv_bfloat16  g_H  [(size_t)RROWS*Cc];        // LN output (GEMM A)
__device__ __nv_bfloat16  g_QKV[(size_t)RROWS*3*Cc];      // qkv bf16
__device__ __nv_bfloat16  g_O  [(size_t)RROWS*Cc];        // attn output bf16
__device__ __nv_bfloat16  g_HID[(size_t)RROWS*HIDN];      // mlp hidden bf16
__device__ __nv_bfloat16  g_Wq [Cc*3*Cc];
__device__ __nv_bfloat16  g_Wp [Cc*Cc];
__device__ __nv_bfloat16  g_W1 [Cc*HIDN];
__device__ __nv_bfloat16  g_W2 [HIDN*Cc];

// ---------------- small helpers ----------------
__device__ __forceinline__ uint32_t smem_u32(const void* p){
    return (uint32_t)__cvta_generic_to_shared(p);
}
__device__ __forceinline__ void cp16(uint32_t s, const void* g){
    asm volatile("cp.async.cg.shared.global [%0], [%1], 16;\n" :: "r"(s), "l"(g));
}
__device__ __forceinline__ void cpcommit(){ asm volatile("cp.async.commit_group;\n"); }
template<int NN> __device__ __forceinline__ void cpwait(){
    asm volatile("cp.async.wait_group %0;\n" :: "n"(NN));
}
__device__ __forceinline__ void ldsm4(uint32_t (&r)[4], uint32_t addr){
    asm volatile("ldmatrix.sync.aligned.m8n8.x4.shared.b16 {%0,%1,%2,%3}, [%4];\n"
        : "=r"(r[0]),"=r"(r[1]),"=r"(r[2]),"=r"(r[3]) : "r"(addr));
}
__device__ __forceinline__ void ldsm4t(uint32_t &r0, uint32_t &r1, uint32_t &r2, uint32_t &r3, uint32_t addr){
    asm volatile("ldmatrix.sync.aligned.m8n8.x4.trans.shared.b16 {%0,%1,%2,%3}, [%4];\n"
        : "=r"(r0),"=r"(r1),"=r"(r2),"=r"(r3) : "r"(addr));
}
__device__ __forceinline__ void mma16816(float (&c)[4], const uint32_t (&a)[4], const uint32_t (&b)[2]){
    asm volatile("mma.sync.aligned.m16n8k16.row.col.f32.bf16.bf16.f32 "
        "{%0,%1,%2,%3}, {%4,%5,%6,%7}, {%8,%9}, {%0,%1,%2,%3};\n"
        : "+f"(c[0]),"+f"(c[1]),"+f"(c[2]),"+f"(c[3])
        : "r"(a[0]),"r"(a[1]),"r"(a[2]),"r"(a[3]), "r"(b[0]),"r"(b[1]));
}
__device__ __forceinline__ float gelu_tanh(float x){
    float x3 = x*x*x;
    return 0.5f*x*(1.f + tanhf(0.79788456080286535588f*(x + 0.044715f*x3)));
}

// ---------------- weight convert fp32 -> bf16 (all 4 in one launch) ----------------
__global__ void cvt_all(const float* __restrict__ wq, const float* __restrict__ wp,
                        const float* __restrict__ w1, const float* __restrict__ w2){
    int i = blockIdx.x*256 + threadIdx.x;
    const int n0 = Cc*3*Cc;            // 196608
    const int n1 = n0 + Cc*Cc;         // 262144
    const int n2 = n1 + Cc*HIDN;       // 524288
    const int n3 = n2 + HIDN*Cc;       // 786432
    if (i < n0)      g_Wq[i]      = __float2bfloat16(wq[i]);
    else if (i < n1) g_Wp[i-n0]   = __float2bfloat16(wp[i-n0]);
    else if (i < n2) g_W1[i-n1]   = __float2bfloat16(w1[i-n1]);
    else if (i < n3) g_W2[i-n2]   = __float2bfloat16(w2[i-n2]);
}

// ---------------- CPE conv + window build ----------------
// SRC=0: token stream from flat arrays (data[N,C], rt[NW,C]).
// SRC=1: token stream from previous block's X buffer (X-layout), rt = Xsrc[w,0,:].
// Writes Xdst (never equal to Xsrc).
template<int SRC>
__global__ void conv_build_x(const float* __restrict__ data, const float* __restrict__ rt,
                             const float* __restrict__ Xsrc, float* __restrict__ Xdst,
                             const float* __restrict__ w3, const float* __restrict__ cb){
    long idx = (long)blockIdx.x*256 + threadIdx.x;
    const long relay = (long)NWIN*Cc;
    if (idx < relay){
        long w = idx >> 8; int c = (int)(idx & 255);
        float v = (SRC == 0) ? rt[idx] : Xsrc[(size_t)w*Ss*Cc + c];
        Xdst[(size_t)w*Ss*Cc + c] = v;
    } else {
        long j = idx - relay;
        long t = j >> 8; int c = (int)(j & 255);
        float x0, xm, xp;
        if (SRC == 0){
            x0 = data[j];
            xm = (t > 0)       ? data[j - Cc] : 0.f;
            xp = (t < NTOK-1)  ? data[j + Cc] : 0.f;
        } else {
            auto ld = [&](long tt) -> float {
                size_t ww = (size_t)(tt >> 5); int kk = (int)(tt & 31);
                return Xsrc[ww*Ss*Cc + (size_t)(1+kk)*Cc + c];
            };
            x0 = ld(t);
            xm = (t > 0)       ? ld(t-1) : 0.f;
            xp = (t < NTOK-1)  ? ld(t+1) : 0.f;
        }
        float val = x0 + xm*w3[c] + x0*w3[Cc+c] + xp*w3[2*Cc+c] + cb[c];
        size_t w = (size_t)(t >> 5); int k = (int)(t & 31);
        Xdst[w*Ss*Cc + (size_t)(1+k)*Cc + c] = val;
    }
}

// ---------------- LayerNorm over C=256, warp per row: X -> g_H (bf16) ----------------
__global__ void __launch_bounds__(256) ln_kernel(const float* __restrict__ X,
                                                 const float* __restrict__ gw,
                                                 const float* __restrict__ bw){
    int warp = threadIdx.x >> 5, lane = threadIdx.x & 31;
    size_t row = (size_t)blockIdx.x*8 + warp;
    const float* x = X + row*Cc;
    float v[8]; float s = 0.f;
    #pragma unroll
    for (int i = 0; i < 8; i++){ v[i] = x[i*32 + lane]; s += v[i]; }
    #pragma unroll
    for (int o = 16; o; o >>= 1) s += __shfl_xor_sync(0xffffffffu, s, o);
    float m = s * (1.f/256.f);
    float vs = 0.f;
    #pragma unroll
    for (int i = 0; i < 8; i++){ float d = v[i]-m; vs += d*d; }
    #pragma unroll
    for (int o = 16; o; o >>= 1) vs += __shfl_xor_sync(0xffffffffu, vs, o);
    float rstd = rsqrtf(vs*(1.f/256.f) + 1e-5f);
    __nv_bfloat16* out = g_H + row*Cc;
    #pragma unroll
    for (int i = 0; i < 8; i++){
        int c = i*32 + lane;
        out[c] = __float2bfloat16((v[i]-m)*rstd*gw[c] + bw[c]);
    }
}

// ---------------- GEMM: C = A(bf16,MxK) @ B(bf16,KxN) + epilogue ----------------
// EPI 0: out_bf16 = val + bias
// EPI 1: out_bf16 = gelu(val + bias)
// EPI 2: Xio += gamma[col] * (val + bias)              (fp32 residual, in place)
// EPI 3: scatter  Xio + gamma*(val+bias)  ->  (outD, outR) final layout (Nn must be 256)
template<int EPI>
__global__ void __launch_bounds__(256) gemm_kernel(
    const __nv_bfloat16* __restrict__ A, const __nv_bfloat16* __restrict__ B,
    const float* __restrict__ bias, const float* __restrict__ gamma,
    float* __restrict__ Xio, __nv_bfloat16* __restrict__ outB,
    float* __restrict__ outD, float* __restrict__ outR,
    int M, int Nn, int Kk)
{
    constexpr int BM = 128, BN = 128, BK = 32;
    constexpr int AP = BK + 8;   // 40  (80B row pitch, 16B-aligned, conflict-light ldmatrix)
    constexpr int BP = BN + 8;   // 136
    __shared__ __nv_bfloat16 As[2][BM*AP];
    __shared__ __nv_bfloat16 Bs[2][BK*BP];

    const int tid = threadIdx.x, lane = tid & 31, warp = tid >> 5;
    const int wm = warp >> 1;    // 0..3  (M)
    const int wn = warp & 1;     // 0..1  (N)
    const size_t mblk = (size_t)blockIdx.y * BM;
    const int    nblk = blockIdx.x * BN;
    const __nv_bfloat16* Ab = A + mblk * (size_t)Kk;
    const __nv_bfloat16* Bb = B + nblk;

    float acc[2][8][4];
    #pragma unroll
    for (int mi = 0; mi < 2; mi++)
        #pragma unroll
        for (int ni = 0; ni < 8; ni++)
            #pragma unroll
            for (int h = 0; h < 4; h++) acc[mi][ni][h] = 0.f;

    const int KT = Kk / BK;
    const int arow0 = tid >> 2, akc = (tid & 3) * 8;
    const int brow0 = tid >> 4, bnc = (tid & 15) * 8;

    auto issue = [&](int kt, int st){
        cp16(smem_u32(&As[st][ arow0     *AP + akc]), Ab + (size_t) arow0     *Kk + kt*BK + akc);
        cp16(smem_u32(&As[st][(arow0+64) *AP + akc]), Ab + (size_t)(arow0+64) *Kk + kt*BK + akc);
        cp16(smem_u32(&Bs[st][ brow0     *BP + bnc]), Bb + (size_t)(kt*BK + brow0     )*Nn + bnc);
        cp16(smem_u32(&Bs[st][(brow0+16) *BP + bnc]), Bb + (size_t)(kt*BK + brow0 + 16)*Nn + bnc);
        cpcommit();
    };

    issue(0, 0);
    const int g = lane >> 3, r = lane & 7;
    for (int kt = 0; kt < KT; kt++){
        const int st = kt & 1;
        if (kt + 1 < KT){ issue(kt+1, st^1); cpwait<1>(); } else { cpwait<0>(); }
        __syncthreads();
        #pragma unroll
        for (int ks = 0; ks < 2; ks++){
            uint32_t a[2][4], b[8][2];
            #pragma unroll
            for (int mi = 0; mi < 2; mi++){
                int row = wm*32 + mi*16 + ((g & 1) ? 8 : 0) + r;
                int col = ks*16 + ((g & 2) ? 8 : 0);
                ldsm4(a[mi], smem_u32(&As[st][row*AP + col]));
            }
            #pragma unroll
            for (int nj = 0; nj < 8; nj += 2){
                int krow = ks*16 + ((g & 1) ? 8 : 0) + r;
                int ncol = wn*64 + nj*8 + ((g & 2) ? 8 : 0);
                ldsm4t(b[nj][0], b[nj][1], b[nj+1][0], b[nj+1][1],
                       smem_u32(&Bs[st][krow*BP + ncol]));
            }
            #pragma unroll
            for (int mi = 0; mi < 2; mi++)
                #pragma unroll
                for (int ni = 0; ni < 8; ni++)
                    mma16816(acc[mi][ni], a[mi], b[ni]);
        }
        __syncthreads();
    }

    // epilogue
    #pragma unroll
    for (int mi = 0; mi < 2; mi++){
        #pragma unroll
        for (int ni = 0; ni < 8; ni++){
            int row = (int)mblk + wm*32 + mi*16 + (lane >> 2);
            int col = nblk + wn*64 + ni*8 + ((lane & 3) << 1);
            float bi0 = bias[col], bi1 = bias[col+1];
            #pragma unroll
            for (int h = 0; h < 2; h++){
                int rr = row + h*8;
                float v0 = acc[mi][ni][h*2+0] + bi0;
                float v1 = acc[mi][ni][h*2+1] + bi1;
                size_t off = (size_t)rr * Nn + col;
                if (EPI == 0){
                    *(__nv_bfloat162*)(outB + off) = __floats2bfloat162_rn(v0, v1);
                } else if (EPI == 1){
                    *(__nv_bfloat162*)(outB + off) =
                        __floats2bfloat162_rn(gelu_tanh(v0), gelu_tanh(v1));
                } else if (EPI == 2){
                    Xio[off]   += gamma[col]   * v0;
                    Xio[off+1] += gamma[col+1] * v1;
                } else {
                    // final: r = x + gamma*ffn, scattered to (data, rt) output layout
                    float r0 = Xio[off]   + gamma[col]   * v0;
                    float r1 = Xio[off+1] + gamma[col+1] * v1;
                    int w = rr / Ss;            // constant divisor
                    int s = rr - w * Ss;
                    if (s == 0){
                        size_t o = (size_t)w*Cc + col;
                        outR[o] = r0; outR[o+1] = r1;
                    } else {
                        size_t o = ((size_t)w*Kw + (s-1))*Cc + col;
                        outD[o] = r0; outD[o+1] = r1;
                    }
                }
            }
        }
    }
}

// ---------------- fused windowed attention: g_QKV -> g_O ----------------
// CTA per window; warp h handles head h. Dynamic smem: q,k,v bf16 [33][258] + scores fp32 [8][33][34]
#define QKV_PITCH 258
#define SC_PITCH  34
#define ATTN_SMEM (((3*Ss*QKV_PITCH*2 + 15)/16)*16 + Hh*Ss*SC_PITCH*4)

__global__ void __launch_bounds__(256) attn_kernel(const float* __restrict__ rpe){
    extern __shared__ char smraw[];
    __nv_bfloat16* sq = (__nv_bfloat16*)smraw;
    __nv_bfloat16* sk = sq + Ss*QKV_PITCH;
    __nv_bfloat16* sv = sk + Ss*QKV_PITCH;
    float* ssc = (float*)(smraw + ((3*Ss*QKV_PITCH*2 + 15)/16)*16);

    const int w = blockIdx.x;
    const int tid = threadIdx.x;
    const __nv_bfloat16* base = g_QKV + (size_t)w * Ss * 3 * Cc;

    for (int i = tid; i < Ss*Cc; i += 256){
        int s = i >> 8, c = i & 255;
        const __nv_bfloat16* p = base + (size_t)s * 3 * Cc;
        sq[s*QKV_PITCH + c] = p[c];
        sk[s*QKV_PITCH + c] = p[Cc + c];
        sv[s*QKV_PITCH + c] = p[2*Cc + c];
    }
    __syncthreads();

    const int warp = tid >> 5, lane = tid & 31;   // warp == head
    const float* rp = rpe + warp * Ss * Ss;

    // scores[h][q][k] = (q.k)*scale + rpe
    for (int idx = lane; idx < Ss*Ss; idx += 32){
        int q = idx / Ss, k = idx - q*Ss;
        const __nv_bfloat16* qp = sq + q*QKV_PITCH + warp*32;
        const __nv_bfloat16* kp = sk + k*QKV_PITCH + warp*32;
        float acc = 0.f;
        #pragma unroll
        for (int d = 0; d < 32; d += 2){
            float2 qf = __bfloat1622float2(*(const __nv_bfloat162*)(qp + d));
            float2 kf = __bfloat1622float2(*(const __nv_bfloat162*)(kp + d));
            acc += qf.x*kf.x + qf.y*kf.y;
        }
        ssc[(warp*Ss + q)*SC_PITCH + k] = acc * SCALE_QK + rp[idx];
    }
    __syncthreads();

    // softmax over k (33) — one row per thread
    for (int rIdx = tid; rIdx < Hh*Ss; rIdx += 256){
        float* row = ssc + rIdx * SC_PITCH;
        float m = -1e30f;
        #pragma unroll
        for (int k = 0; k < Ss; k++) m = fmaxf(m, row[k]);
        float s = 0.f;
        #pragma unroll
        for (int k = 0; k < Ss; k++){ float e = __expf(row[k] - m); row[k] = e; s += e; }
        float inv = 1.f / s;
        #pragma unroll
        for (int k = 0; k < Ss; k++) row[k] *= inv;
    }
    __syncthreads();

    // O[q, h*32+d] = sum_k attn[h][q][k] * v[k][h*32+d]   (lane == d)
    __nv_bfloat16* Ob = g_O + (size_t)w * Ss * Cc + warp*32 + lane;
    for (int q = 0; q < Ss; q++){
        const float* arow = ssc + (warp*Ss + q)*SC_PITCH;
        float acc = 0.f;
        #pragma unroll
        for (int k = 0; k < Ss; k++)
            acc += arow[k] * __bfloat162float(sv[k*QKV_PITCH + warp*32 + lane]);
        Ob[(size_t)q * Cc] = __float2bfloat16(acc);
    }
}

// ---------------- driver ----------------
extern "C" void kernel_launch(void* const* d_in, const int* in_sizes, int n_in,
                              void* d_out, int out_size){
    (void)in_sizes; (void)n_in; (void)out_size;
    const float* data  = (const float*)d_in[0];
    const float* rt    = (const float*)d_in[1];
    const float* cpe_w = (const float*)d_in[2];
    const float* cpe_b = (const float*)d_in[3];
    const float* ln1g  = (const float*)d_in[4];
    const float* ln1b  = (const float*)d_in[5];
    const float* qkvw  = (const float*)d_in[6];
    const float* qkvb  = (const float*)d_in[7];
    const float* rpe   = (const float*)d_in[8];
    const float* projw = (const float*)d_in[9];
    const float* projb = (const float*)d_in[10];
    const float* ln2g  = (const float*)d_in[11];
    const float* ln2b  = (const float*)d_in[12];
    const float* w1    = (const float*)d_in[13];
    const float* b1    = (const float*)d_in[14];
    const float* w2    = (const float*)d_in[15];
    const float* b2    = (const float*)d_in[16];
    const float* gam1  = (const float*)d_in[17];
    const float* gam2  = (const float*)d_in[18];
    float* out = (float*)d_out;

    void *pX1, *pX2, *pH, *pQKV, *pO, *pHID, *pWq, *pWp, *pW1, *pW2;
    cudaGetSymbolAddress(&pX1,  g_X1);
    cudaGetSymbolAddress(&pX2,  g_X2);
    cudaGetSymbolAddress(&pH,   g_H);
    cudaGetSymbolAddress(&pQKV, g_QKV);
    cudaGetSymbolAddress(&pO,   g_O);
    cudaGetSymbolAddress(&pHID, g_HID);
    cudaGetSymbolAddress(&pWq,  g_Wq);
    cudaGetSymbolAddress(&pWp,  g_Wp);
    cudaGetSymbolAddress(&pW1,  g_W1);
    cudaGetSymbolAddress(&pW2,  g_W2);

    cudaFuncSetAttribute(attn_kernel, cudaFuncAttributeMaxDynamicSharedMemorySize, ATTN_SMEM);

    const int EW_GRID = ((long)(NTOK + NWIN) * Cc) / 256;  // 270336
    const int R = RROWS;

    for (int i = 0; i < 2; i++){
        float* X = (float*)(i == 0 ? pX1 : pX2);

        // weights -> bf16 (single launch)
        cvt_all<<<(786432 + 255)/256, 256>>>(
            qkvw + (size_t)i*Cc*3*Cc, projw + (size_t)i*Cc*Cc,
            w1   + (size_t)i*Cc*HIDN, w2   + (size_t)i*HIDN*Cc);

        // cpe + build x (relay + windows)
        if (i == 0)
            conv_build_x<0><<<EW_GRID, 256>>>(data, rt, nullptr, X,
                                              cpe_w, cpe_b);
        else
            conv_build_x<1><<<EW_GRID, 256>>>(nullptr, nullptr, (const float*)pX1, X,
                                              cpe_w + (size_t)3*Cc, cpe_b + (size_t)Cc);

        // ln1 -> g_H
        ln_kernel<<<R/8, 256>>>(X, ln1g + (size_t)i*Cc, ln1b + (size_t)i*Cc);
        // qkv = h @ Wq + b  -> g_QKV (bf16)
        gemm_kernel<0><<<dim3(3*Cc/128, R/128), 256>>>(
            (const __nv_bfloat16*)pH, (const __nv_bfloat16*)pWq,
            qkvb + (size_t)i*3*Cc, nullptr, nullptr, (__nv_bfloat16*)pQKV,
            nullptr, nullptr, R, 3*Cc, Cc);
        // fused windowed attention -> g_O (bf16)
        attn_kernel<<<NWIN, 256, ATTN_SMEM>>>(rpe + (size_t)i*Hh*Ss*Ss);
        // x += gamma1 * (o @ Wp + b)
        gemm_kernel<2><<<dim3(Cc/128, R/128), 256>>>(
            (const __nv_bfloat16*)pO, (const __nv_bfloat16*)pWp,
            projb + (size_t)i*Cc, gam1 + (size_t)i*Cc, X, nullptr,
            nullptr, nullptr, R, Cc, Cc);
        // ln2 -> g_H
        ln_kernel<<<R/8, 256>>>(X, ln2g + (size_t)i*Cc, ln2b + (size_t)i*Cc);
        // hid = gelu(h2 @ W1 + b1) -> g_HID (bf16)
        gemm_kernel<1><<<dim3(HIDN/128, R/128), 256>>>(
            (const __nv_bfloat16*)pH, (const __nv_bfloat16*)pW1,
            b1 + (size_t)i*HIDN, nullptr, nullptr, (__nv_bfloat16*)pHID,
            nullptr, nullptr, R, HIDN, Cc);
        // final residual: block 0 -> X in place; block 1 -> scatter straight to output
        if (i == 0){
            gemm_kernel<2><<<dim3(Cc/128, R/128), 256>>>(
                (const __nv_bfloat16*)pHID, (const __nv_bfloat16*)pW2,
                b2, gam2, X, nullptr, nullptr, nullptr, R, Cc, HIDN);
        } else {
            gemm_kernel<3><<<dim3(Cc/128, R/128), 256>>>(
                (const __nv_bfloat16*)pHID, (const __nv_bfloat16*)pW2,
                b2 + (size_t)HIDN, gam2 + (size_t)Cc, X, nullptr,
                out, out + (size_t)NTOK*Cc, R, Cc, HIDN);
        }
    }
}